// round 12
// baseline (speedup 1.0000x reference)
#include <cuda_runtime.h>
#include <cuda_fp16.h>
#include <math.h>
#include <float.h>
#include <stdint.h>

#define Lc 128
#define Bc 128
#define Ec 300
#define Pc 50
#define FNc 256
#define H2c 100
#define LABc 19

#define XW 1024
#define XROWS (Bc * Lc + 8)
#define WK 5120

__device__ __half g_X[(size_t)XROWS * XW];
__device__ __half g_W[(size_t)768 * WK];
__device__ float g_sf[Bc * 768];
__device__ float g_feat[Bc * 1900];

// ---------------- PTX helpers ----------------
__device__ __forceinline__ uint32_t smem_u32(const void* p) {
    uint32_t a;
    asm("{ .reg .u64 t; cvta.to.shared.u64 t, %1; cvt.u32.u64 %0, t; }" : "=r"(a) : "l"(p));
    return a;
}
__device__ __forceinline__ void cp16(uint32_t saddr, const void* g) {
    asm volatile("cp.async.cg.shared.global [%0], [%1], 16;" :: "r"(saddr), "l"(g) : "memory");
}
#define CP_COMMIT() asm volatile("cp.async.commit_group;" ::: "memory")
#define CP_WAIT0()  asm volatile("cp.async.wait_group 0;" ::: "memory")

#define LDSM4(r0, r1, r2, r3, a)                                              \
    asm volatile("ldmatrix.sync.aligned.m8n8.x4.shared.b16 {%0,%1,%2,%3}, [%4];" \
        : "=r"(r0), "=r"(r1), "=r"(r2), "=r"(r3) : "r"(a))

#define MMA16816(d, a, b)                                                     \
    asm volatile("mma.sync.aligned.m16n8k16.row.col.f32.f16.f16.f32 "         \
        "{%0,%1,%2,%3}, {%4,%5,%6,%7}, {%8,%9}, {%0,%1,%2,%3};"               \
        : "+f"((d)[0]), "+f"((d)[1]), "+f"((d)[2]), "+f"((d)[3])              \
        : "r"((a)[0]), "r"((a)[1]), "r"((a)[2]), "r"((a)[3]),                 \
          "r"((b)[0]), "r"((b)[1]))

// ---------------- fused prep (float4/float2 vectorized) --------------------
__global__ void prep_kernel(const int* __restrict__ inputs,
                            const int* __restrict__ p1, const int* __restrict__ p2,
                            const float* __restrict__ emb,
                            const float* __restrict__ pos1, const float* __restrict__ pos2,
                            const float* __restrict__ w3, const float* __restrict__ w4,
                            const float* __restrict__ w5,
                            const int* __restrict__ e1s, const int* __restrict__ e1e,
                            const int* __restrict__ e2s, const int* __restrict__ e2e) {
    int blk = blockIdx.x;
    if (blk < Bc * Lc) {
        int m = blk;
        int b = m / Lc, t = m % Lc;
        __half2* row = (__half2*)(g_X + (size_t)m * XW);
        int tok0 = (t == 0) ? 0 : inputs[b * Lc + t - 1];
        int tok1 = inputs[b * Lc + t];
        int tok2 = (t + 2 == Lc + 1) ? 0 : inputs[b * Lc + t + 1];
        int i1 = p1[b * Lc + t], i2 = p2[b * Lc + t];
        // work items: 225 float4 chunks (d<900) + 25 + 25 float2 chunks (pos)
        for (int c = threadIdx.x; c < 275; c += blockDim.x) {
            if (c < 225) {
                int d = c * 4;
                float4 v;
                if (t == 0) v = make_float4(0.f, 0.f, 0.f, 0.f);
                else if (d < 300) v = *(const float4*)(emb + (size_t)tok0 * Ec + d);
                else if (d < 600) v = *(const float4*)(emb + (size_t)tok1 * Ec + (d - 300));
                else              v = *(const float4*)(emb + (size_t)tok2 * Ec + (d - 600));
                row[c * 2]     = __floats2half2_rn(v.x, v.y);
                row[c * 2 + 1] = __floats2half2_rn(v.z, v.w);
            } else if (c < 250) {
                int off = (c - 225) * 2;
                float2 v = *(const float2*)(pos1 + (size_t)i1 * Pc + off);
                row[(900 + off) >> 1] = __floats2half2_rn(v.x, v.y);
            } else {
                int off = (c - 250) * 2;
                float2 v = *(const float2*)(pos2 + (size_t)i2 * Pc + off);
                row[(950 + off) >> 1] = __floats2half2_rn(v.x, v.y);
            }
        }
    } else if (blk < Bc * Lc + 768) {
        int fp = blk - Bc * Lc;
        int conv = fp >> 8, f = fp & 255;
        int k = 3 + conv;
        const float* w = (conv == 0) ? w3 : ((conv == 1) ? w4 : w5);
        __half2* dst = (__half2*)(g_W + (size_t)fp * WK);
        for (int i2 = threadIdx.x; i2 < WK / 2; i2 += blockDim.x) {
            int idx = i2 * 2;
            int tap = idx >> 10, d = idx & 1023;
            float2 v = make_float2(0.f, 0.f);
            if (tap < k && d < 1000)
                v = *(const float2*)(w + ((size_t)f * k + tap) * 1000 + d);
            dst[i2] = __floats2half2_rn(v.x, v.y);
        }
    } else {
        int b = blk - Bc * Lc - 768;
        const int* row = inputs + b * Lc;
        int s1 = e1s[b], t1 = e1e[b], s2 = e2s[b], t2 = e2e[b];
        float* fb = g_feat + b * 1900;
        for (int d = threadIdx.x; d < Ec; d += blockDim.x) {
            float a = 0.f;
            for (int i = s1; i <= t1; i++) a += emb[(size_t)row[i] * Ec + d];
            fb[d] = a / (float)(t1 - s1 + 1);
            float c = 0.f;
            for (int i = s2; i <= t2; i++) c += emb[(size_t)row[i] * Ec + d];
            fb[300 + d] = c / (float)(t2 - s2 + 1);
            fb[600 + d]  = emb[(size_t)row[s1 - 1] * Ec + d];
            fb[900 + d]  = emb[(size_t)row[t1 + 1] * Ec + d];
            fb[1200 + d] = emb[(size_t)row[s2 - 1] * Ec + d];
            fb[1500 + d] = emb[(size_t)row[t2 + 1] * Ec + d];
        }
    }
}

// ---------------- fused conv GEMM: R5 tile, super-iteration pipeline -------
// CTA 128x128 per (b, conv, nhalf). 8 warps 4m x 2n, warp tile 32x64
// (mt2 x nt8). BK=32, NSTAGE=4. Per super-iter: one wait0 + one barrier,
// consume stages {2j, 2j+1}, prefetch {2j+2, 2j+3} into the other 2 slots.
#define BK 32
#define ROWB 80
#define OFF_B 10240
#define STAGE 20480
#define NSTAGE 4
#define GEMM_SMEM (NSTAGE * STAGE)

__device__ __forceinline__ void load_stage(uint32_t sb, int buf, int kb, int tid,
                                           size_t brow, int w0) {
    uint32_t s0 = sb + (uint32_t)buf * STAGE;
#pragma unroll
    for (int i = 0; i < 2; i++) {
        int ch = tid * 2 + i;
        int row = ch >> 2, c = ch & 3;
        uint32_t so = (uint32_t)(row * ROWB + c * 16);
        cp16(s0 + so,         g_X + (brow + row) * (size_t)XW + kb * BK + c * 8);
        cp16(s0 + OFF_B + so, g_W + (size_t)(w0 + row) * WK + kb * BK + c * 8);
    }
}

__global__ void __launch_bounds__(256, 2) gemm_kernel() {
    extern __shared__ char smem[];
    __shared__ float red[4][128];
    uint32_t sb = smem_u32(smem);
    int tid = threadIdx.x, lane = tid & 31, warp = tid >> 5;
    int wm = warp & 3, wn = warp >> 2;
    int b = blockIdx.x, nb = blockIdx.z;
    int conv = 2 - blockIdx.y;                // longest jobs (conv5) first
    int f0 = nb * 128;
    size_t brow = (size_t)b * Lc;
    int w0 = conv * 256 + f0;
    int niter = 96 + 32 * conv;               // even
    int nsuper = niter >> 1;

    float d[2][8][4];
#pragma unroll
    for (int mt = 0; mt < 2; mt++)
#pragma unroll
        for (int nt = 0; nt < 8; nt++)
#pragma unroll
            for (int j = 0; j < 4; j++) d[mt][nt][j] = 0.f;

    uint32_t aRel = (uint32_t)((wm * 32 + (lane & 7) + ((lane & 8) ? 8 : 0)) * ROWB
                               + ((lane & 16) ? 16 : 0));
    uint32_t bRel = (uint32_t)(OFF_B
                               + (wn * 64 + (lane & 7) + ((lane & 16) ? 8 : 0)) * ROWB
                               + ((lane & 8) ? 16 : 0));

    // prologue: stages 0,1 as one group
    load_stage(sb, 0, 0, tid, brow, w0);
    load_stage(sb, 1, 1, tid, brow, w0);
    CP_COMMIT();

    for (int j = 0; j < nsuper; j++) {
        CP_WAIT0();
        __syncthreads();
        int pf = 2 * j + 2;
        if (pf < niter) {
            load_stage(sb, pf & (NSTAGE - 1), pf, tid, brow, w0);
            load_stage(sb, (pf + 1) & (NSTAGE - 1), pf + 1, tid, brow, w0);
            CP_COMMIT();
        }
#pragma unroll
        for (int half = 0; half < 2; half++) {
            uint32_t base = sb + (uint32_t)((2 * j + half) & (NSTAGE - 1)) * STAGE;
#pragma unroll
            for (int kc = 0; kc < 2; kc++) {
                uint32_t aH[2][4], bH[8][2];
#pragma unroll
                for (int mt = 0; mt < 2; mt++) {
                    uint32_t ad = base + aRel + mt * (16 * ROWB) + kc * 32;
                    LDSM4(aH[mt][0], aH[mt][1], aH[mt][2], aH[mt][3], ad);
                }
#pragma unroll
                for (int np = 0; np < 4; np++) {
                    uint32_t bd = base + bRel + np * (16 * ROWB) + kc * 32;
                    uint32_t r0, r1, r2, r3;
                    LDSM4(r0, r1, r2, r3, bd);
                    bH[2 * np][0] = r0; bH[2 * np][1] = r1;
                    bH[2 * np + 1][0] = r2; bH[2 * np + 1][1] = r3;
                }
#pragma unroll
                for (int mt = 0; mt < 2; mt++)
#pragma unroll
                    for (int nt = 0; nt < 8; nt++)
                        MMA16816(d[mt][nt], aH[mt], bH[nt]);
            }
        }
    }

    // ---- epilogue: masked max over t ----
    int T = 126 - conv;
    int g = lane >> 2;
#pragma unroll
    for (int nt = 0; nt < 8; nt++) {
        float m0 = -FLT_MAX, m1 = -FLT_MAX;
#pragma unroll
        for (int mt = 0; mt < 2; mt++) {
            int r0 = wm * 32 + mt * 16 + g;
            if (r0 < T)     { m0 = fmaxf(m0, d[mt][nt][0]); m1 = fmaxf(m1, d[mt][nt][1]); }
            if (r0 + 8 < T) { m0 = fmaxf(m0, d[mt][nt][2]); m1 = fmaxf(m1, d[mt][nt][3]); }
        }
#pragma unroll
        for (int off = 4; off < 32; off <<= 1) {
            m0 = fmaxf(m0, __shfl_xor_sync(0xffffffffu, m0, off));
            m1 = fmaxf(m1, __shfl_xor_sync(0xffffffffu, m1, off));
        }
        if (g == 0) {
            int nc = wn * 64 + nt * 8 + (lane & 3) * 2;
            red[wm][nc] = m0;
            red[wm][nc + 1] = m1;
        }
    }
    __syncthreads();
    if (tid < 128) {
        float v = fmaxf(fmaxf(red[0][tid], red[1][tid]),
                        fmaxf(red[2][tid], red[3][tid]));
        g_sf[b * 768 + conv * 256 + f0 + tid] = v;
    }
}

// ---------------- head ----------------
__global__ void mlp_head(const float* __restrict__ cb3, const float* __restrict__ cb4,
                         const float* __restrict__ cb5,
                         const float* __restrict__ W1, const float* __restrict__ b1,
                         const float* __restrict__ W2, const float* __restrict__ b2,
                         float* __restrict__ out) {
    __shared__ float sf[768];
    __shared__ float gbuf[H2c];
    __shared__ float wsum[4][LABc];
    int b = blockIdx.x, tid = threadIdx.x;

    for (int i = tid; i < 768; i += 128) {
        int kf = i >> 8, f = i & 255;
        const float* cb = (kf == 0) ? cb3 : ((kf == 1) ? cb4 : cb5);
        sf[i] = tanhf(g_sf[b * 768 + i] + cb[f]);
    }
    __syncthreads();

    if (tid < H2c) {
        float s = b1[tid];
        const float* w = W1 + tid * 768;
        for (int c = 0; c < 768; c++) s += w[c] * sf[c];
        gbuf[tid] = tanhf(s);
    }
    __syncthreads();

    float part[LABc];
#pragma unroll
    for (int l = 0; l < LABc; l++) part[l] = 0.f;
    const float* fb = g_feat + b * 1900;
    for (int c = tid; c < 1900; c += 128) {
        float v = (c < 1800) ? fb[c] : gbuf[c - 1800];
#pragma unroll
        for (int l = 0; l < LABc; l++) part[l] += v * W2[l * 1900 + c];
    }
    int lane = tid & 31, wid = tid >> 5;
#pragma unroll
    for (int l = 0; l < LABc; l++) {
        float v = part[l];
        for (int s = 16; s; s >>= 1) v += __shfl_down_sync(0xffffffffu, v, s);
        if (lane == 0) wsum[wid][l] = v;
    }
    __syncthreads();
    if (tid < LABc)
        out[b * LABc + tid] = wsum[0][tid] + wsum[1][tid] + wsum[2][tid] + wsum[3][tid] + b2[tid];
}

// ---------------- launch ----------------
extern "C" void kernel_launch(void* const* d_in, const int* in_sizes, int n_in,
                              void* d_out, int out_size) {
    const int* inputs = (const int*)d_in[0];
    const int* e1s = (const int*)d_in[1];
    const int* e1e = (const int*)d_in[2];
    const int* e2s = (const int*)d_in[3];
    const int* e2e = (const int*)d_in[4];
    const int* p1 = (const int*)d_in[5];
    const int* p2 = (const int*)d_in[6];
    const float* emb = (const float*)d_in[7];
    const float* pos1 = (const float*)d_in[8];
    const float* pos2 = (const float*)d_in[9];
    const float* w3 = (const float*)d_in[10];
    const float* cb3 = (const float*)d_in[11];
    const float* w4 = (const float*)d_in[12];
    const float* cb4 = (const float*)d_in[13];
    const float* w5 = (const float*)d_in[14];
    const float* cb5 = (const float*)d_in[15];
    const float* W1 = (const float*)d_in[16];
    const float* b1 = (const float*)d_in[17];
    const float* W2 = (const float*)d_in[18];
    const float* b2 = (const float*)d_in[19];
    float* out = (float*)d_out;

    static int cfg_done = 0;
    if (!cfg_done) {
        cudaFuncSetAttribute(gemm_kernel, cudaFuncAttributeMaxDynamicSharedMemorySize,
                             GEMM_SMEM);
        cfg_done = 1;
    }

    prep_kernel<<<Bc * Lc + 768 + Bc, 256>>>(inputs, p1, p2, emb, pos1, pos2,
                                             w3, w4, w5, e1s, e1e, e2s, e2e);

    dim3 gg(Bc, 3, 2);
    gemm_kernel<<<gg, 256, GEMM_SMEM>>>();

    mlp_head<<<Bc, 128>>>(cb3, cb4, cb5, W1, b1, W2, b2, out);
}

// round 13
// speedup vs baseline: 1.0576x; 1.0576x over previous
#include <cuda_runtime.h>
#include <cuda_fp16.h>
#include <math.h>
#include <float.h>
#include <stdint.h>

#define Lc 128
#define Bc 128
#define Ec 300
#define Pc 50
#define FNc 256
#define H2c 100
#define LABc 19

#define XW 1024
#define XROWS (Bc * Lc + 8)
#define WK 5120

__device__ __half g_X[(size_t)XROWS * XW];
__device__ __half g_W[(size_t)768 * WK];
__device__ float g_sf[Bc * 768];
__device__ float g_feat[Bc * 1900];

// ---------------- PTX helpers ----------------
__device__ __forceinline__ uint32_t smem_u32(const void* p) {
    uint32_t a;
    asm("{ .reg .u64 t; cvta.to.shared.u64 t, %1; cvt.u32.u64 %0, t; }" : "=r"(a) : "l"(p));
    return a;
}
__device__ __forceinline__ void cp16(uint32_t saddr, const void* g) {
    asm volatile("cp.async.cg.shared.global [%0], [%1], 16;" :: "r"(saddr), "l"(g) : "memory");
}
#define CP_COMMIT() asm volatile("cp.async.commit_group;" ::: "memory")
#define CP_WAIT2()  asm volatile("cp.async.wait_group 2;" ::: "memory")

#define LDSM4(r0, r1, r2, r3, a)                                              \
    asm volatile("ldmatrix.sync.aligned.m8n8.x4.shared.b16 {%0,%1,%2,%3}, [%4];" \
        : "=r"(r0), "=r"(r1), "=r"(r2), "=r"(r3) : "r"(a))

#define MMA16816(d, a, b)                                                     \
    asm volatile("mma.sync.aligned.m16n8k16.row.col.f32.f16.f16.f32 "         \
        "{%0,%1,%2,%3}, {%4,%5,%6,%7}, {%8,%9}, {%0,%1,%2,%3};"               \
        : "+f"((d)[0]), "+f"((d)[1]), "+f"((d)[2]), "+f"((d)[3])              \
        : "r"((a)[0]), "r"((a)[1]), "r"((a)[2]), "r"((a)[3]),                 \
          "r"((b)[0]), "r"((b)[1]))

// ---------------- fused prep (float4-vectorized everywhere) ----------------
__global__ void prep_kernel(const int* __restrict__ inputs,
                            const int* __restrict__ p1, const int* __restrict__ p2,
                            const float* __restrict__ emb,
                            const float* __restrict__ pos1, const float* __restrict__ pos2,
                            const float* __restrict__ w3, const float* __restrict__ w4,
                            const float* __restrict__ w5,
                            const int* __restrict__ e1s, const int* __restrict__ e1e,
                            const int* __restrict__ e2s, const int* __restrict__ e2e) {
    int blk = blockIdx.x;
    if (blk < Bc * Lc) {
        int m = blk;
        int b = m / Lc, t = m % Lc;
        __half2* row = (__half2*)(g_X + (size_t)m * XW);
        int tok0 = (t == 0) ? 0 : inputs[b * Lc + t - 1];
        int tok1 = inputs[b * Lc + t];
        int tok2 = (t + 2 == Lc + 1) ? 0 : inputs[b * Lc + t + 1];
        int i1 = p1[b * Lc + t], i2 = p2[b * Lc + t];
        // 225 float4 chunks (d<900) + 25 + 25 float2 chunks (pos segments)
        for (int c = threadIdx.x; c < 275; c += blockDim.x) {
            if (c < 225) {
                int d = c * 4;
                float4 v;
                if (t == 0) v = make_float4(0.f, 0.f, 0.f, 0.f);
                else if (d < 300) v = *(const float4*)(emb + (size_t)tok0 * Ec + d);
                else if (d < 600) v = *(const float4*)(emb + (size_t)tok1 * Ec + (d - 300));
                else              v = *(const float4*)(emb + (size_t)tok2 * Ec + (d - 600));
                row[c * 2]     = __floats2half2_rn(v.x, v.y);
                row[c * 2 + 1] = __floats2half2_rn(v.z, v.w);
            } else if (c < 250) {
                int off = (c - 225) * 2;
                float2 v = *(const float2*)(pos1 + (size_t)i1 * Pc + off);
                row[(900 + off) >> 1] = __floats2half2_rn(v.x, v.y);
            } else {
                int off = (c - 250) * 2;
                float2 v = *(const float2*)(pos2 + (size_t)i2 * Pc + off);
                row[(950 + off) >> 1] = __floats2half2_rn(v.x, v.y);
            }
        }
    } else if (blk < Bc * Lc + 768) {
        int fp = blk - Bc * Lc;
        int conv = fp >> 8, f = fp & 255;
        int k = 3 + conv;
        const float* w = (conv == 0) ? w3 : ((conv == 1) ? w4 : w5);
        __half2* dst = (__half2*)(g_W + (size_t)fp * WK);
        // WK/4 = 1280 float4-sized work items; valid floats are d<1000 per tap
        for (int i4 = threadIdx.x; i4 < WK / 4; i4 += blockDim.x) {
            int idx = i4 * 4;
            int tap = idx >> 10, d = idx & 1023;
            float4 v = make_float4(0.f, 0.f, 0.f, 0.f);
            if (tap < k && d < 1000)       // d multiple of 4; 1000%4==0 -> aligned
                v = *(const float4*)(w + ((size_t)f * k + tap) * 1000 + d);
            dst[i4 * 2]     = __floats2half2_rn(v.x, v.y);
            dst[i4 * 2 + 1] = __floats2half2_rn(v.z, v.w);
        }
    } else {
        int b = blk - Bc * Lc - 768;
        const int* row = inputs + b * Lc;
        int s1 = e1s[b], t1 = e1e[b], s2 = e2s[b], t2 = e2e[b];
        float* fb = g_feat + b * 1900;
        for (int d = threadIdx.x; d < Ec; d += blockDim.x) {
            float a = 0.f;
            for (int i = s1; i <= t1; i++) a += emb[(size_t)row[i] * Ec + d];
            fb[d] = a / (float)(t1 - s1 + 1);
            float c = 0.f;
            for (int i = s2; i <= t2; i++) c += emb[(size_t)row[i] * Ec + d];
            fb[300 + d] = c / (float)(t2 - s2 + 1);
            fb[600 + d]  = emb[(size_t)row[s1 - 1] * Ec + d];
            fb[900 + d]  = emb[(size_t)row[t1 + 1] * Ec + d];
            fb[1200 + d] = emb[(size_t)row[s2 - 1] * Ec + d];
            fb[1500 + d] = emb[(size_t)row[t2 + 1] * Ec + d];
        }
    }
}

// ---------------- fused conv GEMM: R11 champion (verbatim) -----------------
// CTA 128x128 per (b, conv, nhalf). 8 warps 4m x 2n, warp tile 32x64
// (mt2 x nt8). BK=32, 4-stage cp.async ring, wait_group 2, 2 CTAs/SM.
#define BK 32
#define ROWB 80
#define OFF_B 10240
#define STAGE 20480
#define NSTAGE 4
#define GEMM_SMEM (NSTAGE * STAGE)

__device__ __forceinline__ void load_stage(uint32_t sb, int buf, int kb, int tid,
                                           size_t brow, int w0) {
    uint32_t s0 = sb + (uint32_t)buf * STAGE;
#pragma unroll
    for (int i = 0; i < 2; i++) {
        int ch = tid * 2 + i;
        int row = ch >> 2, c = ch & 3;
        uint32_t so = (uint32_t)(row * ROWB + c * 16);
        cp16(s0 + so,         g_X + (brow + row) * (size_t)XW + kb * BK + c * 8);
        cp16(s0 + OFF_B + so, g_W + (size_t)(w0 + row) * WK + kb * BK + c * 8);
    }
}

__global__ void __launch_bounds__(256, 2) gemm_kernel() {
    extern __shared__ char smem[];
    __shared__ float red[4][128];
    uint32_t sb = smem_u32(smem);
    int tid = threadIdx.x, lane = tid & 31, warp = tid >> 5;
    int wm = warp & 3, wn = warp >> 2;
    int b = blockIdx.x, nb = blockIdx.z;
    int conv = 2 - blockIdx.y;                // longest jobs (conv5) first
    int f0 = nb * 128;
    size_t brow = (size_t)b * Lc;
    int w0 = conv * 256 + f0;
    int niter = 96 + 32 * conv;

    float d[2][8][4];
#pragma unroll
    for (int mt = 0; mt < 2; mt++)
#pragma unroll
        for (int nt = 0; nt < 8; nt++)
#pragma unroll
            for (int j = 0; j < 4; j++) d[mt][nt][j] = 0.f;

    uint32_t aRel = (uint32_t)((wm * 32 + (lane & 7) + ((lane & 8) ? 8 : 0)) * ROWB
                               + ((lane & 16) ? 16 : 0));
    uint32_t bRel = (uint32_t)(OFF_B
                               + (wn * 64 + (lane & 7) + ((lane & 16) ? 8 : 0)) * ROWB
                               + ((lane & 8) ? 16 : 0));

    load_stage(sb, 0, 0, tid, brow, w0);
    CP_COMMIT();
    load_stage(sb, 1, 1, tid, brow, w0);
    CP_COMMIT();
    load_stage(sb, 2, 2, tid, brow, w0);
    CP_COMMIT();

    for (int it = 0; it < niter; it++) {
        CP_WAIT2();
        __syncthreads();
        int pf = it + 3;
        if (pf < niter) load_stage(sb, pf & (NSTAGE - 1), pf, tid, brow, w0);
        CP_COMMIT();

        uint32_t base = sb + (uint32_t)(it & (NSTAGE - 1)) * STAGE;
#pragma unroll
        for (int kc = 0; kc < 2; kc++) {
            uint32_t aH[2][4], bH[8][2];
#pragma unroll
            for (int mt = 0; mt < 2; mt++) {
                uint32_t ad = base + aRel + mt * (16 * ROWB) + kc * 32;
                LDSM4(aH[mt][0], aH[mt][1], aH[mt][2], aH[mt][3], ad);
            }
#pragma unroll
            for (int np = 0; np < 4; np++) {
                uint32_t bd = base + bRel + np * (16 * ROWB) + kc * 32;
                uint32_t r0, r1, r2, r3;
                LDSM4(r0, r1, r2, r3, bd);
                bH[2 * np][0] = r0; bH[2 * np][1] = r1;
                bH[2 * np + 1][0] = r2; bH[2 * np + 1][1] = r3;
            }
#pragma unroll
            for (int mt = 0; mt < 2; mt++)
#pragma unroll
                for (int nt = 0; nt < 8; nt++)
                    MMA16816(d[mt][nt], aH[mt], bH[nt]);
        }
    }

    // ---- epilogue: masked max over t ----
    int T = 126 - conv;
    int g = lane >> 2;
#pragma unroll
    for (int nt = 0; nt < 8; nt++) {
        float m0 = -FLT_MAX, m1 = -FLT_MAX;
#pragma unroll
        for (int mt = 0; mt < 2; mt++) {
            int r0 = wm * 32 + mt * 16 + g;
            if (r0 < T)     { m0 = fmaxf(m0, d[mt][nt][0]); m1 = fmaxf(m1, d[mt][nt][1]); }
            if (r0 + 8 < T) { m0 = fmaxf(m0, d[mt][nt][2]); m1 = fmaxf(m1, d[mt][nt][3]); }
        }
#pragma unroll
        for (int off = 4; off < 32; off <<= 1) {
            m0 = fmaxf(m0, __shfl_xor_sync(0xffffffffu, m0, off));
            m1 = fmaxf(m1, __shfl_xor_sync(0xffffffffu, m1, off));
        }
        if (g == 0) {
            int nc = wn * 64 + nt * 8 + (lane & 3) * 2;
            red[wm][nc] = m0;
            red[wm][nc + 1] = m1;
        }
    }
    __syncthreads();
    if (tid < 128) {
        float v = fmaxf(fmaxf(red[0][tid], red[1][tid]),
                        fmaxf(red[2][tid], red[3][tid]));
        g_sf[b * 768 + conv * 256 + f0 + tid] = v;
    }
}

// ---------------- head ----------------
__global__ void mlp_head(const float* __restrict__ cb3, const float* __restrict__ cb4,
                         const float* __restrict__ cb5,
                         const float* __restrict__ W1, const float* __restrict__ b1,
                         const float* __restrict__ W2, const float* __restrict__ b2,
                         float* __restrict__ out) {
    __shared__ float sf[768];
    __shared__ float gbuf[H2c];
    __shared__ float wsum[4][LABc];
    int b = blockIdx.x, tid = threadIdx.x;

    for (int i = tid; i < 768; i += 128) {
        int kf = i >> 8, f = i & 255;
        const float* cb = (kf == 0) ? cb3 : ((kf == 1) ? cb4 : cb5);
        sf[i] = tanhf(g_sf[b * 768 + i] + cb[f]);
    }
    __syncthreads();

    if (tid < H2c) {
        float s = b1[tid];
        const float* w = W1 + tid * 768;
        for (int c = 0; c < 768; c++) s += w[c] * sf[c];
        gbuf[tid] = tanhf(s);
    }
    __syncthreads();

    float part[LABc];
#pragma unroll
    for (int l = 0; l < LABc; l++) part[l] = 0.f;
    const float* fb = g_feat + b * 1900;
    for (int c = tid; c < 1900; c += 128) {
        float v = (c < 1800) ? fb[c] : gbuf[c - 1800];
#pragma unroll
        for (int l = 0; l < LABc; l++) part[l] += v * W2[l * 1900 + c];
    }
    int lane = tid & 31, wid = tid >> 5;
#pragma unroll
    for (int l = 0; l < LABc; l++) {
        float v = part[l];
        for (int s = 16; s; s >>= 1) v += __shfl_down_sync(0xffffffffu, v, s);
        if (lane == 0) wsum[wid][l] = v;
    }
    __syncthreads();
    if (tid < LABc)
        out[b * LABc + tid] = wsum[0][tid] + wsum[1][tid] + wsum[2][tid] + wsum[3][tid] + b2[tid];
}

// ---------------- launch ----------------
extern "C" void kernel_launch(void* const* d_in, const int* in_sizes, int n_in,
                              void* d_out, int out_size) {
    const int* inputs = (const int*)d_in[0];
    const int* e1s = (const int*)d_in[1];
    const int* e1e = (const int*)d_in[2];
    const int* e2s = (const int*)d_in[3];
    const int* e2e = (const int*)d_in[4];
    const int* p1 = (const int*)d_in[5];
    const int* p2 = (const int*)d_in[6];
    const float* emb = (const float*)d_in[7];
    const float* pos1 = (const float*)d_in[8];
    const float* pos2 = (const float*)d_in[9];
    const float* w3 = (const float*)d_in[10];
    const float* cb3 = (const float*)d_in[11];
    const float* w4 = (const float*)d_in[12];
    const float* cb4 = (const float*)d_in[13];
    const float* w5 = (const float*)d_in[14];
    const float* cb5 = (const float*)d_in[15];
    const float* W1 = (const float*)d_in[16];
    const float* b1 = (const float*)d_in[17];
    const float* W2 = (const float*)d_in[18];
    const float* b2 = (const float*)d_in[19];
    float* out = (float*)d_out;

    static int cfg_done = 0;
    if (!cfg_done) {
        cudaFuncSetAttribute(gemm_kernel, cudaFuncAttributeMaxDynamicSharedMemorySize,
                             GEMM_SMEM);
        cfg_done = 1;
    }

    prep_kernel<<<Bc * Lc + 768 + Bc, 256>>>(inputs, p1, p2, emb, pos1, pos2,
                                             w3, w4, w5, e1s, e1e, e2s, e2e);

    dim3 gg(Bc, 3, 2);
    gemm_kernel<<<gg, 256, GEMM_SMEM>>>();

    mlp_head<<<Bc, 128>>>(cb3, cb4, cb5, W1, b1, W2, b2, out);
}

// round 14
// speedup vs baseline: 1.0748x; 1.0162x over previous
#include <cuda_runtime.h>
#include <cuda_fp16.h>
#include <math.h>
#include <float.h>
#include <stdint.h>

#define Lc 128
#define Bc 128
#define Ec 300
#define Pc 50
#define FNc 256
#define H2c 100
#define LABc 19

#define XW 1024
#define XROWS (Bc * Lc + 8)
#define WK 5120

__device__ __half g_X[(size_t)XROWS * XW];
__device__ __half g_W[(size_t)768 * WK];
__device__ float g_sf[Bc * 768];
__device__ float g_feat[Bc * 1900];
__device__ int g_cnt[Bc];              // per-batch gemm-CTA completion counter

// ---------------- PTX helpers ----------------
__device__ __forceinline__ uint32_t smem_u32(const void* p) {
    uint32_t a;
    asm("{ .reg .u64 t; cvta.to.shared.u64 t, %1; cvt.u32.u64 %0, t; }" : "=r"(a) : "l"(p));
    return a;
}
__device__ __forceinline__ void cp16(uint32_t saddr, const void* g) {
    asm volatile("cp.async.cg.shared.global [%0], [%1], 16;" :: "r"(saddr), "l"(g) : "memory");
}
#define CP_COMMIT() asm volatile("cp.async.commit_group;" ::: "memory")
#define CP_WAIT2()  asm volatile("cp.async.wait_group 2;" ::: "memory")

#define LDSM4(r0, r1, r2, r3, a)                                              \
    asm volatile("ldmatrix.sync.aligned.m8n8.x4.shared.b16 {%0,%1,%2,%3}, [%4];" \
        : "=r"(r0), "=r"(r1), "=r"(r2), "=r"(r3) : "r"(a))

#define MMA16816(d, a, b)                                                     \
    asm volatile("mma.sync.aligned.m16n8k16.row.col.f32.f16.f16.f32 "         \
        "{%0,%1,%2,%3}, {%4,%5,%6,%7}, {%8,%9}, {%0,%1,%2,%3};"               \
        : "+f"((d)[0]), "+f"((d)[1]), "+f"((d)[2]), "+f"((d)[3])              \
        : "r"((a)[0]), "r"((a)[1]), "r"((a)[2]), "r"((a)[3]),                 \
          "r"((b)[0]), "r"((b)[1]))

// ---------------- fused prep (float4-vectorized everywhere) ----------------
__global__ void prep_kernel(const int* __restrict__ inputs,
                            const int* __restrict__ p1, const int* __restrict__ p2,
                            const float* __restrict__ emb,
                            const float* __restrict__ pos1, const float* __restrict__ pos2,
                            const float* __restrict__ w3, const float* __restrict__ w4,
                            const float* __restrict__ w5,
                            const int* __restrict__ e1s, const int* __restrict__ e1e,
                            const int* __restrict__ e2s, const int* __restrict__ e2e) {
    int blk = blockIdx.x;
    if (blk < Bc * Lc) {
        int m = blk;
        int b = m / Lc, t = m % Lc;
        __half2* row = (__half2*)(g_X + (size_t)m * XW);
        int tok0 = (t == 0) ? 0 : inputs[b * Lc + t - 1];
        int tok1 = inputs[b * Lc + t];
        int tok2 = (t + 2 == Lc + 1) ? 0 : inputs[b * Lc + t + 1];
        int i1 = p1[b * Lc + t], i2 = p2[b * Lc + t];
        for (int c = threadIdx.x; c < 275; c += blockDim.x) {
            if (c < 225) {
                int d = c * 4;
                float4 v;
                if (t == 0) v = make_float4(0.f, 0.f, 0.f, 0.f);
                else if (d < 300) v = *(const float4*)(emb + (size_t)tok0 * Ec + d);
                else if (d < 600) v = *(const float4*)(emb + (size_t)tok1 * Ec + (d - 300));
                else              v = *(const float4*)(emb + (size_t)tok2 * Ec + (d - 600));
                row[c * 2]     = __floats2half2_rn(v.x, v.y);
                row[c * 2 + 1] = __floats2half2_rn(v.z, v.w);
            } else if (c < 250) {
                int off = (c - 225) * 2;
                float2 v = *(const float2*)(pos1 + (size_t)i1 * Pc + off);
                row[(900 + off) >> 1] = __floats2half2_rn(v.x, v.y);
            } else {
                int off = (c - 250) * 2;
                float2 v = *(const float2*)(pos2 + (size_t)i2 * Pc + off);
                row[(950 + off) >> 1] = __floats2half2_rn(v.x, v.y);
            }
        }
    } else if (blk < Bc * Lc + 768) {
        int fp = blk - Bc * Lc;
        int conv = fp >> 8, f = fp & 255;
        int k = 3 + conv;
        const float* w = (conv == 0) ? w3 : ((conv == 1) ? w4 : w5);
        __half2* dst = (__half2*)(g_W + (size_t)fp * WK);
        for (int i4 = threadIdx.x; i4 < WK / 4; i4 += blockDim.x) {
            int idx = i4 * 4;
            int tap = idx >> 10, d = idx & 1023;
            float4 v = make_float4(0.f, 0.f, 0.f, 0.f);
            if (tap < k && d < 1000)
                v = *(const float4*)(w + ((size_t)f * k + tap) * 1000 + d);
            dst[i4 * 2]     = __floats2half2_rn(v.x, v.y);
            dst[i4 * 2 + 1] = __floats2half2_rn(v.z, v.w);
        }
    } else {
        int b = blk - Bc * Lc - 768;
        const int* row = inputs + b * Lc;
        int s1 = e1s[b], t1 = e1e[b], s2 = e2s[b], t2 = e2e[b];
        float* fb = g_feat + b * 1900;
        if (threadIdx.x == 0) g_cnt[b] = 0;   // reset completion counter
        for (int d = threadIdx.x; d < Ec; d += blockDim.x) {
            float a = 0.f;
            for (int i = s1; i <= t1; i++) a += emb[(size_t)row[i] * Ec + d];
            fb[d] = a / (float)(t1 - s1 + 1);
            float c = 0.f;
            for (int i = s2; i <= t2; i++) c += emb[(size_t)row[i] * Ec + d];
            fb[300 + d] = c / (float)(t2 - s2 + 1);
            fb[600 + d]  = emb[(size_t)row[s1 - 1] * Ec + d];
            fb[900 + d]  = emb[(size_t)row[t1 + 1] * Ec + d];
            fb[1200 + d] = emb[(size_t)row[s2 - 1] * Ec + d];
            fb[1500 + d] = emb[(size_t)row[t2 + 1] * Ec + d];
        }
    }
}

// ---------------- fused conv GEMM + inline head (last CTA per batch) -------
// CTA 128x128 per (b, conv, nhalf). 8 warps 4m x 2n, warp tile 32x64
// (mt2 x nt8). BK=32, 4-stage cp.async ring, wait_group 2, 2 CTAs/SM.
#define BK 32
#define ROWB 80
#define OFF_B 10240
#define STAGE 20480
#define NSTAGE 4
#define GEMM_SMEM (NSTAGE * STAGE)

__device__ __forceinline__ void load_stage(uint32_t sb, int buf, int kb, int tid,
                                           size_t brow, int w0) {
    uint32_t s0 = sb + (uint32_t)buf * STAGE;
#pragma unroll
    for (int i = 0; i < 2; i++) {
        int ch = tid * 2 + i;
        int row = ch >> 2, c = ch & 3;
        uint32_t so = (uint32_t)(row * ROWB + c * 16);
        cp16(s0 + so,         g_X + (brow + row) * (size_t)XW + kb * BK + c * 8);
        cp16(s0 + OFF_B + so, g_W + (size_t)(w0 + row) * WK + kb * BK + c * 8);
    }
}

__global__ void __launch_bounds__(256, 2) gemm_kernel(
        const float* __restrict__ cb3, const float* __restrict__ cb4,
        const float* __restrict__ cb5,
        const float* __restrict__ W1, const float* __restrict__ b1,
        const float* __restrict__ W2, const float* __restrict__ b2,
        float* __restrict__ out) {
    extern __shared__ char smem[];
    __shared__ float red[4][128];
    __shared__ int s_last;
    uint32_t sb = smem_u32(smem);
    int tid = threadIdx.x, lane = tid & 31, warp = tid >> 5;
    int wm = warp & 3, wn = warp >> 2;
    int b = blockIdx.x, nb = blockIdx.z;
    int conv = 2 - blockIdx.y;                // longest jobs (conv5) first
    int f0 = nb * 128;
    size_t brow = (size_t)b * Lc;
    int w0 = conv * 256 + f0;
    int niter = 96 + 32 * conv;

    float d[2][8][4];
#pragma unroll
    for (int mt = 0; mt < 2; mt++)
#pragma unroll
        for (int nt = 0; nt < 8; nt++)
#pragma unroll
            for (int j = 0; j < 4; j++) d[mt][nt][j] = 0.f;

    uint32_t aRel = (uint32_t)((wm * 32 + (lane & 7) + ((lane & 8) ? 8 : 0)) * ROWB
                               + ((lane & 16) ? 16 : 0));
    uint32_t bRel = (uint32_t)(OFF_B
                               + (wn * 64 + (lane & 7) + ((lane & 16) ? 8 : 0)) * ROWB
                               + ((lane & 8) ? 16 : 0));

    load_stage(sb, 0, 0, tid, brow, w0);
    CP_COMMIT();
    load_stage(sb, 1, 1, tid, brow, w0);
    CP_COMMIT();
    load_stage(sb, 2, 2, tid, brow, w0);
    CP_COMMIT();

    for (int it = 0; it < niter; it++) {
        CP_WAIT2();
        __syncthreads();
        int pf = it + 3;
        if (pf < niter) load_stage(sb, pf & (NSTAGE - 1), pf, tid, brow, w0);
        CP_COMMIT();

        uint32_t base = sb + (uint32_t)(it & (NSTAGE - 1)) * STAGE;
#pragma unroll
        for (int kc = 0; kc < 2; kc++) {
            uint32_t aH[2][4], bH[8][2];
#pragma unroll
            for (int mt = 0; mt < 2; mt++) {
                uint32_t ad = base + aRel + mt * (16 * ROWB) + kc * 32;
                LDSM4(aH[mt][0], aH[mt][1], aH[mt][2], aH[mt][3], ad);
            }
#pragma unroll
            for (int np = 0; np < 4; np++) {
                uint32_t bd = base + bRel + np * (16 * ROWB) + kc * 32;
                uint32_t r0, r1, r2, r3;
                LDSM4(r0, r1, r2, r3, bd);
                bH[2 * np][0] = r0; bH[2 * np][1] = r1;
                bH[2 * np + 1][0] = r2; bH[2 * np + 1][1] = r3;
            }
#pragma unroll
            for (int mt = 0; mt < 2; mt++)
#pragma unroll
                for (int nt = 0; nt < 8; nt++)
                    MMA16816(d[mt][nt], aH[mt], bH[nt]);
        }
    }

    // ---- epilogue: masked max over t -> g_sf ----
    int T = 126 - conv;
    int g = lane >> 2;
#pragma unroll
    for (int nt = 0; nt < 8; nt++) {
        float m0 = -FLT_MAX, m1 = -FLT_MAX;
#pragma unroll
        for (int mt = 0; mt < 2; mt++) {
            int r0 = wm * 32 + mt * 16 + g;
            if (r0 < T)     { m0 = fmaxf(m0, d[mt][nt][0]); m1 = fmaxf(m1, d[mt][nt][1]); }
            if (r0 + 8 < T) { m0 = fmaxf(m0, d[mt][nt][2]); m1 = fmaxf(m1, d[mt][nt][3]); }
        }
#pragma unroll
        for (int off = 4; off < 32; off <<= 1) {
            m0 = fmaxf(m0, __shfl_xor_sync(0xffffffffu, m0, off));
            m1 = fmaxf(m1, __shfl_xor_sync(0xffffffffu, m1, off));
        }
        if (g == 0) {
            int nc = wn * 64 + nt * 8 + (lane & 3) * 2;
            red[wm][nc] = m0;
            red[wm][nc + 1] = m1;
        }
    }
    __syncthreads();
    if (tid < 128) {
        float v = fmaxf(fmaxf(red[0][tid], red[1][tid]),
                        fmaxf(red[2][tid], red[3][tid]));
        g_sf[b * 768 + conv * 256 + f0 + tid] = v;
    }

    // ---- completion count: last of the 6 CTAs for batch b runs the head ---
    __threadfence();
    __syncthreads();
    if (tid == 0) {
        int old = atomicAdd(&g_cnt[b], 1);
        s_last = (old == 5);
    }
    __syncthreads();
    if (!s_last) return;
    __threadfence();                          // acquire: see peers' g_sf

    // ---- inline head for batch b (identical math to standalone mlp_head) --
    float* sf   = (float*)smem;               // 768
    float* gbuf = sf + 768;                   // 100
    float* wsum = gbuf + H2c;                 // 4 x 19
    if (tid < 128) {
        for (int i = tid; i < 768; i += 128) {
            int kf = i >> 8, f = i & 255;
            const float* cb = (kf == 0) ? cb3 : ((kf == 1) ? cb4 : cb5);
            sf[i] = tanhf(g_sf[b * 768 + i] + cb[f]);
        }
    }
    __syncthreads();
    if (tid < H2c) {
        float s = b1[tid];
        const float* w = W1 + tid * 768;
        for (int c = 0; c < 768; c++) s += w[c] * sf[c];
        gbuf[tid] = tanhf(s);
    }
    __syncthreads();
    if (tid < 128) {
        float part[LABc];
#pragma unroll
        for (int l = 0; l < LABc; l++) part[l] = 0.f;
        const float* fb = g_feat + b * 1900;
        for (int c = tid; c < 1900; c += 128) {
            float v = (c < 1800) ? fb[c] : gbuf[c - 1800];
#pragma unroll
            for (int l = 0; l < LABc; l++) part[l] += v * W2[l * 1900 + c];
        }
        int wid2 = tid >> 5;
#pragma unroll
        for (int l = 0; l < LABc; l++) {
            float v = part[l];
            for (int s = 16; s; s >>= 1) v += __shfl_down_sync(0xffffffffu, v, s);
            if (lane == 0) wsum[wid2 * LABc + l] = v;
        }
    }
    __syncthreads();
    if (tid < LABc)
        out[b * LABc + tid] = wsum[tid] + wsum[LABc + tid]
                            + wsum[2 * LABc + tid] + wsum[3 * LABc + tid] + b2[tid];
}

// ---------------- launch ----------------
extern "C" void kernel_launch(void* const* d_in, const int* in_sizes, int n_in,
                              void* d_out, int out_size) {
    const int* inputs = (const int*)d_in[0];
    const int* e1s = (const int*)d_in[1];
    const int* e1e = (const int*)d_in[2];
    const int* e2s = (const int*)d_in[3];
    const int* e2e = (const int*)d_in[4];
    const int* p1 = (const int*)d_in[5];
    const int* p2 = (const int*)d_in[6];
    const float* emb = (const float*)d_in[7];
    const float* pos1 = (const float*)d_in[8];
    const float* pos2 = (const float*)d_in[9];
    const float* w3 = (const float*)d_in[10];
    const float* cb3 = (const float*)d_in[11];
    const float* w4 = (const float*)d_in[12];
    const float* cb4 = (const float*)d_in[13];
    const float* w5 = (const float*)d_in[14];
    const float* cb5 = (const float*)d_in[15];
    const float* W1 = (const float*)d_in[16];
    const float* b1 = (const float*)d_in[17];
    const float* W2 = (const float*)d_in[18];
    const float* b2 = (const float*)d_in[19];
    float* out = (float*)d_out;

    static int cfg_done = 0;
    if (!cfg_done) {
        cudaFuncSetAttribute(gemm_kernel, cudaFuncAttributeMaxDynamicSharedMemorySize,
                             GEMM_SMEM);
        cfg_done = 1;
    }

    prep_kernel<<<Bc * Lc + 768 + Bc, 256>>>(inputs, p1, p2, emb, pos1, pos2,
                                             w3, w4, w5, e1s, e1e, e2s, e2e);

    dim3 gg(Bc, 3, 2);
    gemm_kernel<<<gg, 256, GEMM_SMEM>>>(cb3, cb4, cb5, W1, b1, W2, b2, out);
}